// round 1
// baseline (speedup 1.0000x reference)
#include <cuda_runtime.h>
#include <math.h>

#define Hd     1024
#define Vocab  32000
#define NBLK   148
#define NTHR   1024
#define NWARP  32
#define TOTW   (NBLK * NWARP)   // 4736
#define MAXSTEPS 192

// ---------------- persistent device scratch (no allocations allowed) --------
__device__ float g_h0[2][Hd];
__device__ float g_c0[Hd];
__device__ float g_h1[2][Hd];
__device__ float g_c1[Hd];
__device__ unsigned long long g_argmax[MAXSTEPS];
__device__ float g_partial[MAXSTEPS][NBLK];
__device__ unsigned long long g_bar;

__global__ void dec_init()
{
    if (threadIdx.x == 0) g_bar = 0ULL;
    for (int t = threadIdx.x; t < MAXSTEPS; t += blockDim.x) g_argmax[t] = 0ULL;
}

// warp-cooperative dot of a 1024-float weight row against a shared vector
__device__ __forceinline__ float warp_dot(const float* __restrict__ w,
                                          const float* __restrict__ sh,
                                          int lane)
{
    const float4* w4 = reinterpret_cast<const float4*>(w);
    const float4* h4 = reinterpret_cast<const float4*>(sh);
    float acc0 = 0.f, acc1 = 0.f;
#pragma unroll
    for (int it = 0; it < 8; it += 2) {
        float4 a  = w4[it * 32 + lane];
        float4 a2 = w4[(it + 1) * 32 + lane];
        float4 b  = h4[it * 32 + lane];
        float4 b2 = h4[(it + 1) * 32 + lane];
        acc0 += a.x * b.x + a.y * b.y + a.z * b.z + a.w * b.w;
        acc1 += a2.x * b2.x + a2.y * b2.y + a2.z * b2.z + a2.w * b2.w;
    }
    float acc = acc0 + acc1;
#pragma unroll
    for (int o = 16; o; o >>= 1) acc += __shfl_xor_sync(0xffffffffu, acc, o);
    return acc;
}

#define GRID_BARRIER() do {                                                  \
    __syncthreads();                                                         \
    if (tid == 0) {                                                          \
        __threadfence();                                                     \
        atomicAdd(&g_bar, 1ULL);                                             \
        bar_target += (unsigned long long)gridDim.x;                         \
        while (*((volatile unsigned long long*)&g_bar) < bar_target) { }     \
    }                                                                        \
    __syncthreads();                                                         \
} while (0)

__device__ __forceinline__ float sigmoidf_(float x)
{
    return 1.f / (1.f + expf(-x));
}

__global__ void __launch_bounds__(NTHR, 1)
decoder_kernel(const int* __restrict__ y,
               const float* __restrict__ cv,
               const int* __restrict__ stride_p,
               const float* __restrict__ W_up,  const float* __restrict__ b_up,
               const float* __restrict__ W_ih0, const float* __restrict__ W_hh0,
               const float* __restrict__ b_ih0, const float* __restrict__ b_hh0,
               const float* __restrict__ W_ih1, const float* __restrict__ W_hh1,
               const float* __restrict__ b_ih1, const float* __restrict__ b_hh1,
               const float* __restrict__ W_out, const float* __restrict__ b_out,
               float* __restrict__ out)
{
    __shared__ __align__(16) float sh_a[Hd];
    __shared__ __align__(16) float sh_b[Hd];
    __shared__ float sh_red[NWARP];
    __shared__ unsigned long long sh_key[NWARP];
    __shared__ float sh_lse;
    __shared__ float sh_tok;

    const int tid  = threadIdx.x;
    const int bid  = blockIdx.x;
    const int wid  = tid >> 5;
    const int lane = tid & 31;
    const int gw   = bid * NWARP + wid;
    unsigned long long bar_target = 0ULL;

    const int nsteps = *stride_p;

    // ---------------- init: ctx = cv0*cv1 ; h_init = W_up @ ctx + b_up -----
    sh_a[tid] = cv[tid] * cv[Hd + tid];
    __syncthreads();
    {
        int row = wid * NBLK + bid;            // distribute rows over all SMs
        if (row < Hd) {
            float d = warp_dot(W_up + (size_t)row * Hd, sh_a, lane);
            if (lane == 0) {
                float v = d + b_up[row];
                g_h0[0][row] = v; g_c0[row] = v;
                g_h1[0][row] = v; g_c1[row] = v;
            }
        }
    }
    GRID_BARRIER();

    for (int t = 0; t < nsteps; ++t) {
        const int rp = t & 1;
        const int wp = rp ^ 1;

        // ---- phase A prologue: finalize step t-1 (log-softmax) + token ----
        if (t == 0) {
            if (tid == 0) sh_tok = (float)y[0];
            __syncthreads();
        } else {
            if (wid == 0) {
                float s = 0.f;
                for (int k = lane; k < NBLK; k += 32)
                    s += __ldcv(&g_partial[t - 1][k]);
#pragma unroll
                for (int o = 16; o; o >>= 1)
                    s += __shfl_xor_sync(0xffffffffu, s, o);
                if (lane == 0) sh_lse = logf(s);
            }
            if (tid == 32) {
                unsigned long long key =
                    *((volatile unsigned long long*)&g_argmax[t - 1]);
                sh_tok = (float)(0xFFFFFFFFu - (unsigned)(key & 0xFFFFFFFFull));
            }
            __syncthreads();
            float lse = sh_lse;
            int v = bid * NTHR + tid;
            if (v < Vocab) {
                size_t idx = (size_t)(t - 1) * Vocab + v;
                out[idx] = __ldcv(&out[idx]) - lse;
            }
        }
        float tok = sh_tok;

        // ---- phase A: layer-0 LSTM cell (quad-per-warp) ----
        sh_a[tid] = __ldcv(&g_h0[rp][tid]);
        __syncthreads();
        {
            int j = wid * NBLK + bid;
            if (j < Hd) {
                float d0 = warp_dot(W_hh0 + (size_t)(0 * Hd + j) * Hd, sh_a, lane);
                float d1 = warp_dot(W_hh0 + (size_t)(1 * Hd + j) * Hd, sh_a, lane);
                float d2 = warp_dot(W_hh0 + (size_t)(2 * Hd + j) * Hd, sh_a, lane);
                float d3 = warp_dot(W_hh0 + (size_t)(3 * Hd + j) * Hd, sh_a, lane);
                if (lane == 0) {
                    float pi = d0 + b_ih0[j]          + b_hh0[j]          + tok * W_ih0[j];
                    float pf = d1 + b_ih0[Hd + j]     + b_hh0[Hd + j]     + tok * W_ih0[Hd + j];
                    float pg = d2 + b_ih0[2 * Hd + j] + b_hh0[2 * Hd + j] + tok * W_ih0[2 * Hd + j];
                    float po = d3 + b_ih0[3 * Hd + j] + b_hh0[3 * Hd + j] + tok * W_ih0[3 * Hd + j];
                    float ig = sigmoidf_(pi);
                    float fg = sigmoidf_(pf);
                    float gg = tanhf(pg);
                    float og = sigmoidf_(po);
                    float c  = fg * g_c0[j] + ig * gg;
                    g_c0[j] = c;
                    g_h0[wp][j] = og * tanhf(c);
                }
            }
        }
        GRID_BARRIER();

        // ---- phase B: layer-1 LSTM cell ----
        sh_a[tid] = __ldcv(&g_h0[wp][tid]);
        sh_b[tid] = __ldcv(&g_h1[rp][tid]);
        __syncthreads();
        {
            int j = wid * NBLK + bid;
            if (j < Hd) {
                float d[4];
#pragma unroll 1
                for (int g = 0; g < 4; ++g) {
                    size_t row = (size_t)(g * Hd + j);
                    d[g] = warp_dot(W_ih1 + row * Hd, sh_a, lane)
                         + warp_dot(W_hh1 + row * Hd, sh_b, lane);
                }
                if (lane == 0) {
                    float pi = d[0] + b_ih1[j]          + b_hh1[j];
                    float pf = d[1] + b_ih1[Hd + j]     + b_hh1[Hd + j];
                    float pg = d[2] + b_ih1[2 * Hd + j] + b_hh1[2 * Hd + j];
                    float po = d[3] + b_ih1[3 * Hd + j] + b_hh1[3 * Hd + j];
                    float ig = sigmoidf_(pi);
                    float fg = sigmoidf_(pf);
                    float gg = tanhf(pg);
                    float og = sigmoidf_(po);
                    float c  = fg * g_c1[j] + ig * gg;
                    g_c1[j] = c;
                    g_h1[wp][j] = og * tanhf(c);
                }
            }
        }
        GRID_BARRIER();

        // ---- phase C: vocab head: preds, per-block argmax + sumexp ----
        sh_a[tid] = __ldcv(&g_h1[wp][tid]);
        __syncthreads();
        float sumExp = 0.f;
        unsigned long long bestKey = 0ULL;
        for (int r = gw; r < Vocab; r += TOTW) {
            float d = warp_dot(W_out + (size_t)r * Hd, sh_a, lane);
            if (lane == 0) {
                float p = fmaxf(d + b_out[r], 0.f);
                out[(size_t)t * Vocab + r] = p;
                sumExp += expf(p);
                unsigned long long key =
                    ((unsigned long long)__float_as_uint(p) << 32)
                    | (unsigned long long)(0xFFFFFFFFu - (unsigned)r);
                if (key > bestKey) bestKey = key;
            }
        }
        if (lane == 0) { sh_red[wid] = sumExp; sh_key[wid] = bestKey; }
        __syncthreads();
        if (wid == 0) {
            float s = sh_red[lane];
            unsigned long long k = sh_key[lane];
#pragma unroll
            for (int o = 16; o; o >>= 1) {
                s += __shfl_xor_sync(0xffffffffu, s, o);
                unsigned long long k2 = __shfl_xor_sync(0xffffffffu, k, o);
                if (k2 > k) k = k2;
            }
            if (lane == 0) {
                g_partial[t][bid] = s;
                atomicMax(&g_argmax[t], k);
            }
        }
        GRID_BARRIER();
    }

    // ---- final log-softmax finalize for the last step ----
    {
        if (wid == 0) {
            float s = 0.f;
            for (int k = lane; k < NBLK; k += 32)
                s += __ldcv(&g_partial[nsteps - 1][k]);
#pragma unroll
            for (int o = 16; o; o >>= 1)
                s += __shfl_xor_sync(0xffffffffu, s, o);
            if (lane == 0) sh_lse = logf(s);
        }
        __syncthreads();
        float lse = sh_lse;
        int v = bid * NTHR + tid;
        if (v < Vocab) {
            size_t idx = (size_t)(nsteps - 1) * Vocab + v;
            out[idx] = __ldcv(&out[idx]) - lse;
        }
    }
}

extern "C" void kernel_launch(void* const* d_in, const int* in_sizes, int n_in,
                              void* d_out, int out_size)
{
    (void)in_sizes; (void)n_in; (void)out_size;
    dec_init<<<1, 256>>>();
    decoder_kernel<<<NBLK, NTHR>>>(
        (const int*)  d_in[0],   // y
        (const float*)d_in[1],   // context_vector
        (const int*)  d_in[2],   // stride
        (const float*)d_in[3],  (const float*)d_in[4],    // W_up, b_up
        (const float*)d_in[5],  (const float*)d_in[6],    // W_ih0, W_hh0
        (const float*)d_in[7],  (const float*)d_in[8],    // b_ih0, b_hh0
        (const float*)d_in[9],  (const float*)d_in[10],   // W_ih1, W_hh1
        (const float*)d_in[11], (const float*)d_in[12],   // b_ih1, b_hh1
        (const float*)d_in[13], (const float*)d_in[14],   // W_out, b_out
        (float*)d_out);
}

// round 2
// speedup vs baseline: 1.4496x; 1.4496x over previous
#include <cuda_runtime.h>
#include <math.h>

#define Hd     1024
#define G4     4096
#define Vocab  32000
#define NBLK   148
#define NTHR   1024
#define NWARP  32
#define TOTW   (NBLK * NWARP)   // 4736
#define MAXSTEPS 192

// ---------------- persistent device scratch (no allocations allowed) --------
__device__ float g_gate0[G4];
__device__ float g_gate1[G4];
__device__ float g_hinit[Hd];
__device__ unsigned long long g_argmax[MAXSTEPS];
__device__ float g_partial[MAXSTEPS][NBLK];
__device__ unsigned long long g_bar;

__global__ void dec_init()
{
    if (threadIdx.x == 0) g_bar = 0ULL;
    for (int t = threadIdx.x; t < MAXSTEPS; t += blockDim.x) g_argmax[t] = 0ULL;
}

__device__ __forceinline__ float sigmoidf_(float x)
{
    return 1.f / (1.f + expf(-x));
}

__device__ __forceinline__ float warp_reduce_add(float v)
{
#pragma unroll
    for (int o = 16; o; o >>= 1) v += __shfl_xor_sync(0xffffffffu, v, o);
    return v;
}

// warp-cooperative dot of one 1024-float weight row against a shared vector
__device__ __forceinline__ float warp_dot(const float* __restrict__ w,
                                          const float* __restrict__ sh,
                                          int lane)
{
    const float4* w4 = reinterpret_cast<const float4*>(w);
    const float4* h4 = reinterpret_cast<const float4*>(sh);
    float a0 = 0.f, a1 = 0.f;
#pragma unroll
    for (int it = 0; it < 8; it += 2) {
        float4 x = w4[it * 32 + lane];
        float4 y = w4[(it + 1) * 32 + lane];
        float4 u = h4[it * 32 + lane];
        float4 v = h4[(it + 1) * 32 + lane];
        a0 += x.x * u.x + x.y * u.y + x.z * u.z + x.w * u.w;
        a1 += y.x * v.x + y.y * v.y + y.z * v.z + y.w * v.w;
    }
    return warp_reduce_add(a0 + a1);
}

// fused dot: w1·s1 + w2·s2 with one reduce (layer-1 gate)
__device__ __forceinline__ float warp_dot2(const float* __restrict__ w1,
                                           const float* __restrict__ s1,
                                           const float* __restrict__ w2,
                                           const float* __restrict__ s2,
                                           int lane)
{
    const float4* a4 = reinterpret_cast<const float4*>(w1);
    const float4* h4 = reinterpret_cast<const float4*>(s1);
    const float4* b4 = reinterpret_cast<const float4*>(w2);
    const float4* g4 = reinterpret_cast<const float4*>(s2);
    float p = 0.f, q = 0.f;
#pragma unroll
    for (int it = 0; it < 8; ++it) {
        float4 a = a4[it * 32 + lane];
        float4 h = h4[it * 32 + lane];
        float4 b = b4[it * 32 + lane];
        float4 g = g4[it * 32 + lane];
        p += a.x * h.x + a.y * h.y + a.z * h.z + a.w * h.w;
        q += b.x * g.x + b.y * g.y + b.z * g.z + b.w * g.w;
    }
    return warp_reduce_add(p + q);
}

// two independent rows against the same shared vector, interleaved reduces
__device__ __forceinline__ void warp_dot_pair(const float* __restrict__ w1,
                                              const float* __restrict__ w2,
                                              const float* __restrict__ sh,
                                              int lane, float& o1, float& o2)
{
    const float4* a4 = reinterpret_cast<const float4*>(w1);
    const float4* b4 = reinterpret_cast<const float4*>(w2);
    const float4* h4 = reinterpret_cast<const float4*>(sh);
    float p = 0.f, q = 0.f;
#pragma unroll
    for (int it = 0; it < 8; ++it) {
        float4 h = h4[it * 32 + lane];
        float4 a = a4[it * 32 + lane];
        float4 b = b4[it * 32 + lane];
        p += a.x * h.x + a.y * h.y + a.z * h.z + a.w * h.w;
        q += b.x * h.x + b.y * h.y + b.z * h.z + b.w * h.w;
    }
#pragma unroll
    for (int o = 16; o; o >>= 1) {
        p += __shfl_xor_sync(0xffffffffu, p, o);
        q += __shfl_xor_sync(0xffffffffu, q, o);
    }
    o1 = p; o2 = q;
}

#define GRID_BARRIER() do {                                                  \
    __syncthreads();                                                         \
    if (tid == 0) {                                                          \
        __threadfence();                                                     \
        atomicAdd(&g_bar, 1ULL);                                             \
        bar_target += (unsigned long long)gridDim.x;                         \
        while (*((volatile unsigned long long*)&g_bar) < bar_target) { }     \
    }                                                                        \
    __syncthreads();                                                         \
} while (0)

__global__ void __launch_bounds__(NTHR, 1)
decoder_kernel(const int* __restrict__ y,
               const float* __restrict__ cv,
               const int* __restrict__ stride_p,
               const float* __restrict__ W_up,  const float* __restrict__ b_up,
               const float* __restrict__ W_ih0, const float* __restrict__ W_hh0,
               const float* __restrict__ b_ih0, const float* __restrict__ b_hh0,
               const float* __restrict__ W_ih1, const float* __restrict__ W_hh1,
               const float* __restrict__ b_ih1, const float* __restrict__ b_hh1,
               const float* __restrict__ W_out, const float* __restrict__ b_out,
               float* __restrict__ out)
{
    __shared__ __align__(16) float sh_h0[Hd];
    __shared__ __align__(16) float sh_h1[Hd];
    __shared__ __align__(16) float sh_c0[Hd];
    __shared__ __align__(16) float sh_c1[Hd];
    __shared__ float sh_red[NWARP];
    __shared__ unsigned long long sh_key[NWARP];
    __shared__ float sh_lse;

    const int tid  = threadIdx.x;
    const int bid  = blockIdx.x;
    const int wid  = tid >> 5;
    const int lane = tid & 31;
    const int gw   = bid * NWARP + wid;
    unsigned long long bar_target = 0ULL;

    const int nsteps = *stride_p;

    // ---------------- init: ctx = cv0*cv1 ; h_init = W_up @ ctx + b_up -----
    sh_h0[tid] = cv[tid] * cv[Hd + tid];
    __syncthreads();
    {
        int row = wid * NBLK + bid;
        if (row < Hd) {
            float d = warp_dot(W_up + (size_t)row * Hd, sh_h0, lane);
            if (lane == 0) g_hinit[row] = d + b_up[row];
        }
    }
    GRID_BARRIER();
    {
        float hv = __ldcv(&g_hinit[tid]);
        sh_h0[tid] = hv; sh_c0[tid] = hv; sh_h1[tid] = hv; sh_c1[tid] = hv;
    }
    __syncthreads();

    const int jrow = wid * NBLK + bid;   // gate row for phases A/B (balanced)

    for (int t = 0; t < nsteps; ++t) {
        // ---- prologue (overlapped with A dots): warp0 reduces prev lse ----
        if (t > 0 && wid == 0) {
            float s = 0.f;
            for (int k = lane; k < NBLK; k += 32)
                s += __ldcv(&g_partial[t - 1][k]);
            s = warp_reduce_add(s);
            if (lane == 0) sh_lse = logf(s);
        }

        // ---- phase A: layer-0 gate pre-activations, 1 row per warp ----
        if (jrow < G4) {
            float d = warp_dot(W_hh0 + (size_t)jrow * Hd, sh_h0, lane);
            if (lane == 0) {
                float tokf;
                if (t == 0) {
                    tokf = (float)__ldg(&y[0]);
                } else {
                    unsigned long long key = __ldcv(&g_argmax[t - 1]);
                    tokf = (float)(0xFFFFFFFFu - (unsigned)(key & 0xFFFFFFFFull));
                }
                g_gate0[jrow] = d + b_ih0[jrow] + b_hh0[jrow] + tokf * W_ih0[jrow];
            }
        }
        GRID_BARRIER();

        // ---- A2: finalize log-softmax of step t-1 + layer-0 cell (redundant/block)
        if (t > 0) {
            int v = bid * NTHR + tid;
            if (v < Vocab) {
                size_t idx = (size_t)(t - 1) * Vocab + v;
                out[idx] = __ldcv(&out[idx]) - sh_lse;
            }
        }
        {
            float pi = __ldcv(&g_gate0[tid]);
            float pf = __ldcv(&g_gate0[Hd + tid]);
            float pg = __ldcv(&g_gate0[2 * Hd + tid]);
            float po = __ldcv(&g_gate0[3 * Hd + tid]);
            float ig = sigmoidf_(pi);
            float fg = sigmoidf_(pf);
            float gg = tanhf(pg);
            float og = sigmoidf_(po);
            float c  = fg * sh_c0[tid] + ig * gg;
            sh_c0[tid] = c;
            sh_h0[tid] = og * tanhf(c);
        }
        __syncthreads();

        // ---- phase B: layer-1 gate pre-activations, 1 row per warp ----
        if (jrow < G4) {
            float d = warp_dot2(W_ih1 + (size_t)jrow * Hd, sh_h0,
                                W_hh1 + (size_t)jrow * Hd, sh_h1, lane);
            if (lane == 0) g_gate1[jrow] = d + b_ih1[jrow] + b_hh1[jrow];
        }
        GRID_BARRIER();

        // ---- B2: layer-1 cell (redundant/block) ----
        {
            float pi = __ldcv(&g_gate1[tid]);
            float pf = __ldcv(&g_gate1[Hd + tid]);
            float pg = __ldcv(&g_gate1[2 * Hd + tid]);
            float po = __ldcv(&g_gate1[3 * Hd + tid]);
            float ig = sigmoidf_(pi);
            float fg = sigmoidf_(pf);
            float gg = tanhf(pg);
            float og = sigmoidf_(po);
            float c  = fg * sh_c1[tid] + ig * gg;
            sh_c1[tid] = c;
            sh_h1[tid] = og * tanhf(c);
        }
        __syncthreads();

        // ---- phase C: vocab head, two rows per warp-iteration ----
        float sumExp = 0.f;
        unsigned long long bestKey = 0ULL;
        int r = gw;
        while (r + TOTW < Vocab) {
            float d0, d1;
            warp_dot_pair(W_out + (size_t)r * Hd,
                          W_out + (size_t)(r + TOTW) * Hd, sh_h1, lane, d0, d1);
            if (lane == 0) {
                float p0 = fmaxf(d0 + b_out[r], 0.f);
                float p1 = fmaxf(d1 + b_out[r + TOTW], 0.f);
                out[(size_t)t * Vocab + r] = p0;
                out[(size_t)t * Vocab + r + TOTW] = p1;
                sumExp += expf(p0) + expf(p1);
                unsigned long long k0 =
                    ((unsigned long long)__float_as_uint(p0) << 32)
                    | (unsigned long long)(0xFFFFFFFFu - (unsigned)r);
                unsigned long long k1 =
                    ((unsigned long long)__float_as_uint(p1) << 32)
                    | (unsigned long long)(0xFFFFFFFFu - (unsigned)(r + TOTW));
                if (k0 > bestKey) bestKey = k0;
                if (k1 > bestKey) bestKey = k1;
            }
            r += 2 * TOTW;
        }
        if (r < Vocab) {
            float d = warp_dot(W_out + (size_t)r * Hd, sh_h1, lane);
            if (lane == 0) {
                float p = fmaxf(d + b_out[r], 0.f);
                out[(size_t)t * Vocab + r] = p;
                sumExp += expf(p);
                unsigned long long k =
                    ((unsigned long long)__float_as_uint(p) << 32)
                    | (unsigned long long)(0xFFFFFFFFu - (unsigned)r);
                if (k > bestKey) bestKey = k;
            }
        }
        if (lane == 0) { sh_red[wid] = sumExp; sh_key[wid] = bestKey; }
        __syncthreads();
        if (wid == 0) {
            float s = sh_red[lane];
            unsigned long long k = sh_key[lane];
#pragma unroll
            for (int o = 16; o; o >>= 1) {
                s += __shfl_xor_sync(0xffffffffu, s, o);
                unsigned long long k2 = __shfl_xor_sync(0xffffffffu, k, o);
                if (k2 > k) k = k2;
            }
            if (lane == 0) {
                g_partial[t][bid] = s;
                atomicMax(&g_argmax[t], k);
            }
        }
        GRID_BARRIER();
    }

    // ---- final log-softmax finalize for the last step ----
    if (wid == 0) {
        float s = 0.f;
        for (int k = lane; k < NBLK; k += 32)
            s += __ldcv(&g_partial[nsteps - 1][k]);
        s = warp_reduce_add(s);
        if (lane == 0) sh_lse = logf(s);
    }
    __syncthreads();
    {
        int v = bid * NTHR + tid;
        if (v < Vocab) {
            size_t idx = (size_t)(nsteps - 1) * Vocab + v;
            out[idx] = __ldcv(&out[idx]) - sh_lse;
        }
    }
}

extern "C" void kernel_launch(void* const* d_in, const int* in_sizes, int n_in,
                              void* d_out, int out_size)
{
    (void)in_sizes; (void)n_in; (void)out_size;
    dec_init<<<1, 256>>>();
    decoder_kernel<<<NBLK, NTHR>>>(
        (const int*)  d_in[0],   // y
        (const float*)d_in[1],   // context_vector
        (const int*)  d_in[2],   // stride
        (const float*)d_in[3],  (const float*)d_in[4],    // W_up, b_up
        (const float*)d_in[5],  (const float*)d_in[6],    // W_ih0, W_hh0
        (const float*)d_in[7],  (const float*)d_in[8],    // b_ih0, b_hh0
        (const float*)d_in[9],  (const float*)d_in[10],   // W_ih1, W_hh1
        (const float*)d_in[11], (const float*)d_in[12],   // b_ih1, b_hh1
        (const float*)d_in[13], (const float*)d_in[14],   // W_out, b_out
        (float*)d_out);
}

// round 3
// speedup vs baseline: 1.4747x; 1.0173x over previous
#include <cuda_runtime.h>
#include <math.h>

#define Hd     1024
#define G4     4096
#define Vocab  32000
#define NBLK   148
#define NTHR   1024
#define NWARP  32
#define TOTW   (NBLK * NWARP)   // 4736
#define MAXSTEPS 192

// ---------------- persistent device scratch (no allocations allowed) --------
__device__ float g_gate0[G4];     // layer-0 gate pre-act (W_hh0·h0 + biases), token term added later
__device__ float g_gate1[G4];     // layer-1 gate pre-act (full)
__device__ float g_hinit[Hd];
__device__ unsigned long long g_argmax[MAXSTEPS];
__device__ float g_partial[MAXSTEPS][NBLK];
__device__ unsigned long long g_bar;

__global__ void dec_init()
{
    if (threadIdx.x == 0) g_bar = 0ULL;
    for (int t = threadIdx.x; t < MAXSTEPS; t += blockDim.x) g_argmax[t] = 0ULL;
}

__device__ __forceinline__ float sigmoidf_(float x)
{
    return 1.f / (1.f + expf(-x));
}

__device__ __forceinline__ float warp_reduce_add(float v)
{
#pragma unroll
    for (int o = 16; o; o >>= 1) v += __shfl_xor_sync(0xffffffffu, v, o);
    return v;
}

// warp-cooperative dot of one 1024-float weight row against a shared vector
__device__ __forceinline__ float warp_dot(const float* __restrict__ w,
                                          const float* __restrict__ sh,
                                          int lane)
{
    const float4* w4 = reinterpret_cast<const float4*>(w);
    const float4* h4 = reinterpret_cast<const float4*>(sh);
    float a0 = 0.f, a1 = 0.f;
#pragma unroll
    for (int it = 0; it < 8; it += 2) {
        float4 x = w4[it * 32 + lane];
        float4 y = w4[(it + 1) * 32 + lane];
        float4 u = h4[it * 32 + lane];
        float4 v = h4[(it + 1) * 32 + lane];
        a0 += x.x * u.x + x.y * u.y + x.z * u.z + x.w * u.w;
        a1 += y.x * v.x + y.y * v.y + y.z * v.z + y.w * v.w;
    }
    return warp_reduce_add(a0 + a1);
}

// two rows against two different vectors, separate (interleaved) reduces
__device__ __forceinline__ void warp_dot_pair2(const float* __restrict__ w1,
                                               const float* __restrict__ s1,
                                               const float* __restrict__ w2,
                                               const float* __restrict__ s2,
                                               int lane, float& o1, float& o2)
{
    const float4* a4 = reinterpret_cast<const float4*>(w1);
    const float4* h4 = reinterpret_cast<const float4*>(s1);
    const float4* b4 = reinterpret_cast<const float4*>(w2);
    const float4* g4 = reinterpret_cast<const float4*>(s2);
    float p = 0.f, q = 0.f;
#pragma unroll
    for (int it = 0; it < 8; ++it) {
        float4 a = a4[it * 32 + lane];
        float4 h = h4[it * 32 + lane];
        float4 b = b4[it * 32 + lane];
        float4 g = g4[it * 32 + lane];
        p += a.x * h.x + a.y * h.y + a.z * h.z + a.w * h.w;
        q += b.x * g.x + b.y * g.y + b.z * g.z + b.w * g.w;
    }
#pragma unroll
    for (int o = 16; o; o >>= 1) {
        p += __shfl_xor_sync(0xffffffffu, p, o);
        q += __shfl_xor_sync(0xffffffffu, q, o);
    }
    o1 = p; o2 = q;
}

// two independent rows against the same shared vector, interleaved reduces
__device__ __forceinline__ void warp_dot_pair(const float* __restrict__ w1,
                                              const float* __restrict__ w2,
                                              const float* __restrict__ sh,
                                              int lane, float& o1, float& o2)
{
    const float4* a4 = reinterpret_cast<const float4*>(w1);
    const float4* b4 = reinterpret_cast<const float4*>(w2);
    const float4* h4 = reinterpret_cast<const float4*>(sh);
    float p = 0.f, q = 0.f;
#pragma unroll
    for (int it = 0; it < 8; ++it) {
        float4 h = h4[it * 32 + lane];
        float4 a = a4[it * 32 + lane];
        float4 b = b4[it * 32 + lane];
        p += a.x * h.x + a.y * h.y + a.z * h.z + a.w * h.w;
        q += b.x * h.x + b.y * h.y + b.z * h.z + b.w * h.w;
    }
#pragma unroll
    for (int o = 16; o; o >>= 1) {
        p += __shfl_xor_sync(0xffffffffu, p, o);
        q += __shfl_xor_sync(0xffffffffu, q, o);
    }
    o1 = p; o2 = q;
}

#define GRID_BARRIER() do {                                                  \
    __syncthreads();                                                         \
    if (tid == 0) {                                                          \
        __threadfence();                                                     \
        atomicAdd(&g_bar, 1ULL);                                             \
        bar_target += (unsigned long long)gridDim.x;                         \
        while (*((volatile unsigned long long*)&g_bar) < bar_target) { }     \
    }                                                                        \
    __syncthreads();                                                         \
} while (0)

__global__ void __launch_bounds__(NTHR, 1)
decoder_kernel(const int* __restrict__ y,
               const float* __restrict__ cv,
               const int* __restrict__ stride_p,
               const float* __restrict__ W_up,  const float* __restrict__ b_up,
               const float* __restrict__ W_ih0, const float* __restrict__ W_hh0,
               const float* __restrict__ b_ih0, const float* __restrict__ b_hh0,
               const float* __restrict__ W_ih1, const float* __restrict__ W_hh1,
               const float* __restrict__ b_ih1, const float* __restrict__ b_hh1,
               const float* __restrict__ W_out, const float* __restrict__ b_out,
               float* __restrict__ out)
{
    __shared__ __align__(16) float sh_h0[Hd];
    __shared__ __align__(16) float sh_h1[Hd];
    __shared__ __align__(16) float sh_c0[Hd];
    __shared__ __align__(16) float sh_c1[Hd];
    __shared__ float sh_red[NWARP];
    __shared__ unsigned long long sh_key[NWARP];
    __shared__ float sh_lse;

    const int tid  = threadIdx.x;
    const int bid  = blockIdx.x;
    const int wid  = tid >> 5;
    const int lane = tid & 31;
    const int gw   = bid * NWARP + wid;
    unsigned long long bar_target = 0ULL;

    const int nsteps = *stride_p;
    const int jrow = wid * NBLK + bid;   // gate row owned by this warp

    // ---------------- init: ctx = cv0*cv1 ; h_init = W_up @ ctx + b_up -----
    sh_h0[tid] = cv[tid] * cv[Hd + tid];
    __syncthreads();
    {
        int row = jrow;
        if (row < Hd) {
            float d = warp_dot(W_up + (size_t)row * Hd, sh_h0, lane);
            if (lane == 0) g_hinit[row] = d + b_up[row];
        }
    }
    GRID_BARRIER();
    {
        float hv = __ldcv(&g_hinit[tid]);
        sh_h0[tid] = hv; sh_c0[tid] = hv; sh_h1[tid] = hv; sh_c1[tid] = hv;
    }
    __syncthreads();

    // initial recurrent dots for step 0 (hh0 -> g_gate0, hh1 partial -> reg)
    float q1 = 0.f;
    if (jrow < G4) {
        float p, q;
        warp_dot_pair2(W_hh0 + (size_t)jrow * Hd, sh_h0,
                       W_hh1 + (size_t)jrow * Hd, sh_h1, lane, p, q);
        q1 = q;
        if (lane == 0)
            g_gate0[jrow] = p + b_ih0[jrow] + b_hh0[jrow];
    }
    GRID_BARRIER();

    for (int t = 0; t < nsteps; ++t) {
        // ---- A2: token, lse reduce (warp0), layer-0 cell (block-redundant) ----
        float tok;
        if (t == 0) {
            tok = (float)__ldg(&y[0]);
        } else {
            unsigned long long key = __ldcv(&g_argmax[t - 1]);
            tok = (float)(0xFFFFFFFFu - (unsigned)(key & 0xFFFFFFFFull));
        }
        if (t > 0 && wid == 0) {
            float s = 0.f;
            for (int k = lane; k < NBLK; k += 32)
                s += __ldcv(&g_partial[t - 1][k]);
            s = warp_reduce_add(s);
            if (lane == 0) sh_lse = logf(s);
        }
        {
            float pi = __ldcv(&g_gate0[tid])          + tok * __ldg(&W_ih0[tid]);
            float pf = __ldcv(&g_gate0[Hd + tid])     + tok * __ldg(&W_ih0[Hd + tid]);
            float pg = __ldcv(&g_gate0[2 * Hd + tid]) + tok * __ldg(&W_ih0[2 * Hd + tid]);
            float po = __ldcv(&g_gate0[3 * Hd + tid]) + tok * __ldg(&W_ih0[3 * Hd + tid]);
            float ig = sigmoidf_(pi);
            float fg = sigmoidf_(pf);
            float gg = tanhf(pg);
            float og = sigmoidf_(po);
            float c  = fg * sh_c0[tid] + ig * gg;
            sh_c0[tid] = c;
            sh_h0[tid] = og * tanhf(c);
        }
        __syncthreads();

        // ---- overlap: finalize log-softmax of step t-1 (stores overlap B) ----
        if (t > 0) {
            int v = bid * NTHR + tid;
            if (v < Vocab) {
                size_t idx = (size_t)(t - 1) * Vocab + v;
                out[idx] = __ldcv(&out[idx]) - sh_lse;
            }
        }

        // ---- phase B: only W_ih1·h0 on the critical path ----
        if (jrow < G4) {
            float d = warp_dot(W_ih1 + (size_t)jrow * Hd, sh_h0, lane);
            if (lane == 0)
                g_gate1[jrow] = q1 + d + b_ih1[jrow] + b_hh1[jrow];
        }
        GRID_BARRIER();

        // ---- B2: layer-1 cell (block-redundant) ----
        {
            float pi = __ldcv(&g_gate1[tid]);
            float pf = __ldcv(&g_gate1[Hd + tid]);
            float pg = __ldcv(&g_gate1[2 * Hd + tid]);
            float po = __ldcv(&g_gate1[3 * Hd + tid]);
            float ig = sigmoidf_(pi);
            float fg = sigmoidf_(pf);
            float gg = tanhf(pg);
            float og = sigmoidf_(po);
            float c  = fg * sh_c1[tid] + ig * gg;
            sh_c1[tid] = c;
            sh_h1[tid] = og * tanhf(c);
        }
        __syncthreads();

        // ---- phase C: recurrent dots for step t+1 + vocab head ----
        if (jrow < G4) {
            float p, q;
            warp_dot_pair2(W_hh0 + (size_t)jrow * Hd, sh_h0,
                           W_hh1 + (size_t)jrow * Hd, sh_h1, lane, p, q);
            q1 = q;
            if (lane == 0)
                g_gate0[jrow] = p + b_ih0[jrow] + b_hh0[jrow];
        }

        float sumExp = 0.f;
        unsigned long long bestKey = 0ULL;
        int r = gw;
        while (r + TOTW < Vocab) {
            float d0, d1;
            warp_dot_pair(W_out + (size_t)r * Hd,
                          W_out + (size_t)(r + TOTW) * Hd, sh_h1, lane, d0, d1);
            if (lane == 0) {
                float p0 = fmaxf(d0 + b_out[r], 0.f);
                float p1 = fmaxf(d1 + b_out[r + TOTW], 0.f);
                out[(size_t)t * Vocab + r] = p0;
                out[(size_t)t * Vocab + r + TOTW] = p1;
                sumExp += expf(p0) + expf(p1);
                unsigned long long k0 =
                    ((unsigned long long)__float_as_uint(p0) << 32)
                    | (unsigned long long)(0xFFFFFFFFu - (unsigned)r);
                unsigned long long k1 =
                    ((unsigned long long)__float_as_uint(p1) << 32)
                    | (unsigned long long)(0xFFFFFFFFu - (unsigned)(r + TOTW));
                if (k0 > bestKey) bestKey = k0;
                if (k1 > bestKey) bestKey = k1;
            }
            r += 2 * TOTW;
        }
        if (r < Vocab) {
            float d = warp_dot(W_out + (size_t)r * Hd, sh_h1, lane);
            if (lane == 0) {
                float p = fmaxf(d + b_out[r], 0.f);
                out[(size_t)t * Vocab + r] = p;
                sumExp += expf(p);
                unsigned long long k =
                    ((unsigned long long)__float_as_uint(p) << 32)
                    | (unsigned long long)(0xFFFFFFFFu - (unsigned)r);
                if (k > bestKey) bestKey = k;
            }
        }
        if (lane == 0) { sh_red[wid] = sumExp; sh_key[wid] = bestKey; }
        __syncthreads();
        if (wid == 0) {
            float s = sh_red[lane];
            unsigned long long k = sh_key[lane];
#pragma unroll
            for (int o = 16; o; o >>= 1) {
                s += __shfl_xor_sync(0xffffffffu, s, o);
                unsigned long long k2 = __shfl_xor_sync(0xffffffffu, k, o);
                if (k2 > k) k = k2;
            }
            if (lane == 0) {
                g_partial[t][bid] = s;
                atomicMax(&g_argmax[t], k);
            }
        }
        GRID_BARRIER();
    }

    // ---- final log-softmax finalize for the last step ----
    if (wid == 0) {
        float s = 0.f;
        for (int k = lane; k < NBLK; k += 32)
            s += __ldcv(&g_partial[nsteps - 1][k]);
        s = warp_reduce_add(s);
        if (lane == 0) sh_lse = logf(s);
    }
    __syncthreads();
    {
        int v = bid * NTHR + tid;
        if (v < Vocab) {
            size_t idx = (size_t)(nsteps - 1) * Vocab + v;
            out[idx] = __ldcv(&out[idx]) - sh_lse;
        }
    }
}

extern "C" void kernel_launch(void* const* d_in, const int* in_sizes, int n_in,
                              void* d_out, int out_size)
{
    (void)in_sizes; (void)n_in; (void)out_size;
    dec_init<<<1, 256>>>();
    decoder_kernel<<<NBLK, NTHR>>>(
        (const int*)  d_in[0],   // y
        (const float*)d_in[1],   // context_vector
        (const int*)  d_in[2],   // stride
        (const float*)d_in[3],  (const float*)d_in[4],    // W_up, b_up
        (const float*)d_in[5],  (const float*)d_in[6],    // W_ih0, W_hh0
        (const float*)d_in[7],  (const float*)d_in[8],    // b_ih0, b_hh0
        (const float*)d_in[9],  (const float*)d_in[10],   // W_ih1, W_hh1
        (const float*)d_in[11], (const float*)d_in[12],   // b_ih1, b_hh1
        (const float*)d_in[13], (const float*)d_in[14],   // W_out, b_out
        (float*)d_out);
}

// round 4
// speedup vs baseline: 1.8333x; 1.2432x over previous
#include <cuda_runtime.h>
#include <math.h>

#define Hd     1024
#define G4     4096
#define Vocab  32000
#define NBLK   148
#define NTHR   1024
#define NWARP  32
#define TOTW   (NBLK * NWARP)   // 4736
#define MAXSTEPS 192

// ---------------- persistent device scratch (no allocations allowed) --------
__device__ float g_gate0[G4];     // layer-0 gate pre-act (W_hh0·h0 + biases)
__device__ float g_gate1[G4];     // layer-1 gate pre-act (full)
__device__ float g_hinit[Hd];
__device__ unsigned long long g_argmax[MAXSTEPS];
__device__ float g_partial[MAXSTEPS][NBLK];
__device__ unsigned long long g_bar;

__global__ void dec_init()
{
    if (threadIdx.x == 0) g_bar = 0ULL;
    for (int t = threadIdx.x; t < MAXSTEPS; t += blockDim.x) g_argmax[t] = 0ULL;
}

__device__ __forceinline__ float sigmoidf_(float x)
{
    return 1.f / (1.f + expf(-x));
}

__device__ __forceinline__ float warp_reduce_add(float v)
{
#pragma unroll
    for (int o = 16; o; o >>= 1) v += __shfl_xor_sync(0xffffffffu, v, o);
    return v;
}

// warp-cooperative dot of one 1024-float weight row against a shared vector
__device__ __forceinline__ float warp_dot(const float* __restrict__ w,
                                          const float* __restrict__ sh,
                                          int lane)
{
    const float4* w4 = reinterpret_cast<const float4*>(w);
    const float4* h4 = reinterpret_cast<const float4*>(sh);
    float a0 = 0.f, a1 = 0.f;
#pragma unroll
    for (int it = 0; it < 8; it += 2) {
        float4 x = w4[it * 32 + lane];
        float4 y = w4[(it + 1) * 32 + lane];
        float4 u = h4[it * 32 + lane];
        float4 v = h4[(it + 1) * 32 + lane];
        a0 += x.x * u.x + x.y * u.y + x.z * u.z + x.w * u.w;
        a1 += y.x * v.x + y.y * v.y + y.z * v.z + y.w * v.w;
    }
    return warp_reduce_add(a0 + a1);
}

// same, but streaming (evict-first) loads for W_out
__device__ __forceinline__ float warp_dot_cs(const float* __restrict__ w,
                                             const float* __restrict__ sh,
                                             int lane)
{
    const float4* w4 = reinterpret_cast<const float4*>(w);
    const float4* h4 = reinterpret_cast<const float4*>(sh);
    float a0 = 0.f, a1 = 0.f;
#pragma unroll
    for (int it = 0; it < 8; it += 2) {
        float4 x = __ldcs(&w4[it * 32 + lane]);
        float4 y = __ldcs(&w4[(it + 1) * 32 + lane]);
        float4 u = h4[it * 32 + lane];
        float4 v = h4[(it + 1) * 32 + lane];
        a0 += x.x * u.x + x.y * u.y + x.z * u.z + x.w * u.w;
        a1 += y.x * v.x + y.y * v.y + y.z * v.z + y.w * v.w;
    }
    return warp_reduce_add(a0 + a1);
}

// two rows against two different vectors, interleaved reduces (recurrent dots)
__device__ __forceinline__ void warp_dot_pair2(const float* __restrict__ w1,
                                               const float* __restrict__ s1,
                                               const float* __restrict__ w2,
                                               const float* __restrict__ s2,
                                               int lane, float& o1, float& o2)
{
    const float4* a4 = reinterpret_cast<const float4*>(w1);
    const float4* h4 = reinterpret_cast<const float4*>(s1);
    const float4* b4 = reinterpret_cast<const float4*>(w2);
    const float4* g4 = reinterpret_cast<const float4*>(s2);
    float p = 0.f, q = 0.f;
#pragma unroll
    for (int it = 0; it < 8; ++it) {
        float4 a = a4[it * 32 + lane];
        float4 h = h4[it * 32 + lane];
        float4 b = b4[it * 32 + lane];
        float4 g = g4[it * 32 + lane];
        p += a.x * h.x + a.y * h.y + a.z * h.z + a.w * h.w;
        q += b.x * g.x + b.y * g.y + b.z * g.z + b.w * g.w;
    }
#pragma unroll
    for (int o = 16; o; o >>= 1) {
        p += __shfl_xor_sync(0xffffffffu, p, o);
        q += __shfl_xor_sync(0xffffffffu, q, o);
    }
    o1 = p; o2 = q;
}

// two independent W_out rows against the same vector (streaming loads)
__device__ __forceinline__ void warp_dot_pair_cs(const float* __restrict__ w1,
                                                 const float* __restrict__ w2,
                                                 const float* __restrict__ sh,
                                                 int lane, float& o1, float& o2)
{
    const float4* a4 = reinterpret_cast<const float4*>(w1);
    const float4* b4 = reinterpret_cast<const float4*>(w2);
    const float4* h4 = reinterpret_cast<const float4*>(sh);
    float p = 0.f, q = 0.f;
#pragma unroll
    for (int it = 0; it < 8; ++it) {
        float4 h = h4[it * 32 + lane];
        float4 a = __ldcs(&a4[it * 32 + lane]);
        float4 b = __ldcs(&b4[it * 32 + lane]);
        p += a.x * h.x + a.y * h.y + a.z * h.z + a.w * h.w;
        q += b.x * h.x + b.y * h.y + b.z * h.z + b.w * h.w;
    }
#pragma unroll
    for (int o = 16; o; o >>= 1) {
        p += __shfl_xor_sync(0xffffffffu, p, o);
        q += __shfl_xor_sync(0xffffffffu, q, o);
    }
    o1 = p; o2 = q;
}

#define GRID_BARRIER() do {                                                  \
    __syncthreads();                                                         \
    if (tid == 0) {                                                          \
        __threadfence();                                                     \
        atomicAdd(&g_bar, 1ULL);                                             \
        bar_target += (unsigned long long)gridDim.x;                         \
        while (*((volatile unsigned long long*)&g_bar) < bar_target) { }     \
    }                                                                        \
    __syncthreads();                                                         \
} while (0)

__global__ void __launch_bounds__(NTHR, 1)
decoder_kernel(const int* __restrict__ y,
               const float* __restrict__ cv,
               const int* __restrict__ stride_p,
               const float* __restrict__ W_up,  const float* __restrict__ b_up,
               const float* __restrict__ W_ih0, const float* __restrict__ W_hh0,
               const float* __restrict__ b_ih0, const float* __restrict__ b_hh0,
               const float* __restrict__ W_ih1, const float* __restrict__ W_hh1,
               const float* __restrict__ b_ih1, const float* __restrict__ b_hh1,
               const float* __restrict__ W_out, const float* __restrict__ b_out,
               float* __restrict__ out)
{
    __shared__ __align__(16) float sh_h0[Hd];
    __shared__ __align__(16) float sh_h1[Hd];
    __shared__ __align__(16) float sh_c0[Hd];
    __shared__ __align__(16) float sh_c1[Hd];
    __shared__ float sh_pred[NWARP][8];   // per-warp deferred relu preds
    __shared__ float sh_red[NWARP];
    __shared__ unsigned long long sh_key[NWARP];
    __shared__ float sh_lse;

    const int tid  = threadIdx.x;
    const int bid  = blockIdx.x;
    const int wid  = tid >> 5;
    const int lane = tid & 31;
    const int gw   = bid * NWARP + wid;
    unsigned long long bar_target = 0ULL;

    const int nsteps = *stride_p;
    const int jrow = wid * NBLK + bid;   // gate row owned by this warp

    // ---------------- init: ctx = cv0*cv1 ; h_init = W_up @ ctx + b_up -----
    sh_h0[tid] = cv[tid] * cv[Hd + tid];
    __syncthreads();
    if (jrow < Hd) {
        float d = warp_dot(W_up + (size_t)jrow * Hd, sh_h0, lane);
        if (lane == 0) g_hinit[jrow] = d + b_up[jrow];
    }
    GRID_BARRIER();
    {
        float hv = __ldcv(&g_hinit[tid]);
        sh_h0[tid] = hv; sh_c0[tid] = hv; sh_h1[tid] = hv; sh_c1[tid] = hv;
    }
    __syncthreads();

    // initial recurrent dots for step 0 (hh0 -> g_gate0, hh1 partial -> reg)
    float q1 = 0.f;
    if (jrow < G4) {
        float p, q;
        warp_dot_pair2(W_hh0 + (size_t)jrow * Hd, sh_h0,
                       W_hh1 + (size_t)jrow * Hd, sh_h1, lane, p, q);
        q1 = q;
        if (lane == 0)
            g_gate0[jrow] = p + b_ih0[jrow] + b_hh0[jrow];
    }
    GRID_BARRIER();

    for (int t = 0; t < nsteps; ++t) {
        // ---- A2: token, lse reduce (warp0), layer-0 cell (block-redundant) ----
        float tok;
        if (t == 0) {
            tok = (float)__ldg(&y[0]);
        } else {
            unsigned long long key = __ldcv(&g_argmax[t - 1]);
            tok = (float)(0xFFFFFFFFu - (unsigned)(key & 0xFFFFFFFFull));
        }
        if (t > 0 && wid == 0) {
            float s = 0.f;
            for (int k = lane; k < NBLK; k += 32)
                s += __ldcv(&g_partial[t - 1][k]);
            s = warp_reduce_add(s);
            if (lane == 0) sh_lse = logf(s);
        }
        {
            float pi = __ldcv(&g_gate0[tid])          + tok * __ldg(&W_ih0[tid]);
            float pf = __ldcv(&g_gate0[Hd + tid])     + tok * __ldg(&W_ih0[Hd + tid]);
            float pg = __ldcv(&g_gate0[2 * Hd + tid]) + tok * __ldg(&W_ih0[2 * Hd + tid]);
            float po = __ldcv(&g_gate0[3 * Hd + tid]) + tok * __ldg(&W_ih0[3 * Hd + tid]);
            float ig = sigmoidf_(pi);
            float fg = sigmoidf_(pf);
            float gg = tanhf(pg);
            float og = sigmoidf_(po);
            float c  = fg * sh_c0[tid] + ig * gg;
            sh_c0[tid] = c;
            sh_h0[tid] = og * tanhf(c);
        }
        __syncthreads();

        // ---- deferred coalesced write of step t-1 log-softmax ----
        if (t > 0 && wid < 7) {
            int r = bid * NWARP + lane + wid * TOTW;
            if (r < Vocab) {
                float v = sh_pred[lane][wid] - sh_lse;
                __stcs(&out[(size_t)(t - 1) * Vocab + r], v);
            }
        }

        // ---- phase B: only W_ih1·h0 on the critical path ----
        if (jrow < G4) {
            float d = warp_dot(W_ih1 + (size_t)jrow * Hd, sh_h0, lane);
            if (lane == 0)
                g_gate1[jrow] = q1 + d + b_ih1[jrow] + b_hh1[jrow];
        }
        GRID_BARRIER();

        // ---- B2: layer-1 cell (block-redundant) ----
        {
            float pi = __ldcv(&g_gate1[tid]);
            float pf = __ldcv(&g_gate1[Hd + tid]);
            float pg = __ldcv(&g_gate1[2 * Hd + tid]);
            float po = __ldcv(&g_gate1[3 * Hd + tid]);
            float ig = sigmoidf_(pi);
            float fg = sigmoidf_(pf);
            float gg = tanhf(pg);
            float og = sigmoidf_(po);
            float c  = fg * sh_c1[tid] + ig * gg;
            sh_c1[tid] = c;
            sh_h1[tid] = og * tanhf(c);
        }
        __syncthreads();

        // ---- phase C: recurrent dots for step t+1 + vocab head ----
        if (jrow < G4) {
            float p, q;
            warp_dot_pair2(W_hh0 + (size_t)jrow * Hd, sh_h0,
                           W_hh1 + (size_t)jrow * Hd, sh_h1, lane, p, q);
            q1 = q;
            if (lane == 0)
                g_gate0[jrow] = p + b_ih0[jrow] + b_hh0[jrow];
        }

        float sumExp = 0.f;
        unsigned long long bestKey = 0ULL;
        int r = gw;
        int k = 0;
        while (r + TOTW < Vocab) {
            float d0, d1;
            warp_dot_pair_cs(W_out + (size_t)r * Hd,
                             W_out + (size_t)(r + TOTW) * Hd, sh_h1, lane, d0, d1);
            if (lane == 0) {
                float p0 = fmaxf(d0 + b_out[r], 0.f);
                float p1 = fmaxf(d1 + b_out[r + TOTW], 0.f);
                sh_pred[wid][k]     = p0;
                sh_pred[wid][k + 1] = p1;
                sumExp += expf(p0) + expf(p1);
                unsigned long long k0 =
                    ((unsigned long long)__float_as_uint(p0) << 32)
                    | (unsigned long long)(0xFFFFFFFFu - (unsigned)r);
                unsigned long long k1 =
                    ((unsigned long long)__float_as_uint(p1) << 32)
                    | (unsigned long long)(0xFFFFFFFFu - (unsigned)(r + TOTW));
                if (k0 > bestKey) bestKey = k0;
                if (k1 > bestKey) bestKey = k1;
            }
            r += 2 * TOTW;
            k += 2;
        }
        if (r < Vocab) {
            float d = warp_dot_cs(W_out + (size_t)r * Hd, sh_h1, lane);
            if (lane == 0) {
                float p = fmaxf(d + b_out[r], 0.f);
                sh_pred[wid][k] = p;
                sumExp += expf(p);
                unsigned long long kk =
                    ((unsigned long long)__float_as_uint(p) << 32)
                    | (unsigned long long)(0xFFFFFFFFu - (unsigned)r);
                if (kk > bestKey) bestKey = kk;
            }
        }
        if (lane == 0) { sh_red[wid] = sumExp; sh_key[wid] = bestKey; }
        __syncthreads();
        if (wid == 0) {
            float s = sh_red[lane];
            unsigned long long kk = sh_key[lane];
#pragma unroll
            for (int o = 16; o; o >>= 1) {
                s += __shfl_xor_sync(0xffffffffu, s, o);
                unsigned long long k2 = __shfl_xor_sync(0xffffffffu, kk, o);
                if (k2 > kk) kk = k2;
            }
            if (lane == 0) {
                g_partial[t][bid] = s;
                atomicMax(&g_argmax[t], kk);
            }
        }
        GRID_BARRIER();
    }

    // ---- final: lse + deferred write for the last step ----
    if (wid == 0) {
        float s = 0.f;
        for (int kk = lane; kk < NBLK; kk += 32)
            s += __ldcv(&g_partial[nsteps - 1][kk]);
        s = warp_reduce_add(s);
        if (lane == 0) sh_lse = logf(s);
    }
    __syncthreads();
    if (wid < 7) {
        int r = bid * NWARP + lane + wid * TOTW;
        if (r < Vocab) {
            float v = sh_pred[lane][wid] - sh_lse;
            __stcs(&out[(size_t)(nsteps - 1) * Vocab + r], v);
        }
    }
}

extern "C" void kernel_launch(void* const* d_in, const int* in_sizes, int n_in,
                              void* d_out, int out_size)
{
    (void)in_sizes; (void)n_in; (void)out_size;
    dec_init<<<1, 256>>>();
    decoder_kernel<<<NBLK, NTHR>>>(
        (const int*)  d_in[0],   // y
        (const float*)d_in[1],   // context_vector
        (const int*)  d_in[2],   // stride
        (const float*)d_in[3],  (const float*)d_in[4],    // W_up, b_up
        (const float*)d_in[5],  (const float*)d_in[6],    // W_ih0, W_hh0
        (const float*)d_in[7],  (const float*)d_in[8],    // b_ih0, b_hh0
        (const float*)d_in[9],  (const float*)d_in[10],   // W_ih1, W_hh1
        (const float*)d_in[11], (const float*)d_in[12],   // b_ih1, b_hh1
        (const float*)d_in[13], (const float*)d_in[14],   // W_out, b_out
        (float*)d_out);
}

// round 7
// speedup vs baseline: 1.9192x; 1.0468x over previous
#include <cuda_runtime.h>
#include <math.h>

#define Hd     1024
#define G4     4096
#define Vocab  32000
#define NBLK   148
#define NTHR   1024
#define NWARP  32
#define TOTW   (NBLK * NWARP)   // 4736
#define MAXSTEPS 192

// ---------------- persistent device scratch (no allocations allowed) --------
__device__ float g_gate0[G4];     // layer-0 gate pre-act (W_hh0·h0 + biases)
__device__ float g_gate1[G4];     // layer-1 gate pre-act (full)
__device__ float g_hinit[Hd];
__device__ unsigned long long g_argmax[MAXSTEPS];
__device__ float g_partial[MAXSTEPS][NBLK];
__device__ unsigned long long g_bar;

__global__ void dec_init()
{
    if (threadIdx.x == 0) g_bar = 0ULL;
    for (int t = threadIdx.x; t < MAXSTEPS; t += blockDim.x) g_argmax[t] = 0ULL;
}

__device__ __forceinline__ float sigmoidf_(float x)
{
    return 1.f / (1.f + expf(-x));
}

__device__ __forceinline__ float warp_reduce_add(float v)
{
#pragma unroll
    for (int o = 16; o; o >>= 1) v += __shfl_xor_sync(0xffffffffu, v, o);
    return v;
}

// ---- 256-bit L2 eviction-policy loads (sm_103a: evict_* needs v8.b32) ------
struct F8 { float v[8]; };

__device__ __forceinline__ F8 ld256_evl(const float* p)   // keep in L2
{
    unsigned r0, r1, r2, r3, r4, r5, r6, r7;
    asm("ld.global.nc.L2::evict_last.v8.b32 {%0,%1,%2,%3,%4,%5,%6,%7}, [%8];"
        : "=r"(r0), "=r"(r1), "=r"(r2), "=r"(r3),
          "=r"(r4), "=r"(r5), "=r"(r6), "=r"(r7)
        : "l"(p));
    F8 f;
    f.v[0] = __uint_as_float(r0); f.v[1] = __uint_as_float(r1);
    f.v[2] = __uint_as_float(r2); f.v[3] = __uint_as_float(r3);
    f.v[4] = __uint_as_float(r4); f.v[5] = __uint_as_float(r5);
    f.v[6] = __uint_as_float(r6); f.v[7] = __uint_as_float(r7);
    return f;
}

__device__ __forceinline__ F8 ld256_evf(const float* p)   // stream through L2
{
    unsigned r0, r1, r2, r3, r4, r5, r6, r7;
    asm("ld.global.nc.L2::evict_first.v8.b32 {%0,%1,%2,%3,%4,%5,%6,%7}, [%8];"
        : "=r"(r0), "=r"(r1), "=r"(r2), "=r"(r3),
          "=r"(r4), "=r"(r5), "=r"(r6), "=r"(r7)
        : "l"(p));
    F8 f;
    f.v[0] = __uint_as_float(r0); f.v[1] = __uint_as_float(r1);
    f.v[2] = __uint_as_float(r2); f.v[3] = __uint_as_float(r3);
    f.v[4] = __uint_as_float(r4); f.v[5] = __uint_as_float(r5);
    f.v[6] = __uint_as_float(r6); f.v[7] = __uint_as_float(r7);
    return f;
}

__device__ __forceinline__ float f8_dot_sh(const F8& a, const float4* h4,
                                           int base)
{
    float4 u0 = h4[base];
    float4 u1 = h4[base + 1];
    return a.v[0] * u0.x + a.v[1] * u0.y + a.v[2] * u0.z + a.v[3] * u0.w
         + a.v[4] * u1.x + a.v[5] * u1.y + a.v[6] * u1.z + a.v[7] * u1.w;
}

// plain warp dot (init only)
__device__ __forceinline__ float warp_dot(const float* __restrict__ w,
                                          const float* __restrict__ sh,
                                          int lane)
{
    const float4* w4 = reinterpret_cast<const float4*>(w);
    const float4* h4 = reinterpret_cast<const float4*>(sh);
    float a0 = 0.f;
#pragma unroll
    for (int it = 0; it < 8; ++it) {
        float4 x = w4[it * 32 + lane];
        float4 u = h4[it * 32 + lane];
        a0 += x.x * u.x + x.y * u.y + x.z * u.z + x.w * u.w;
    }
    return warp_reduce_add(a0);
}

// L2-resident (evict_last) warp dot — LSTM weights
__device__ __forceinline__ float warp_dot_evl(const float* __restrict__ w,
                                              const float* __restrict__ sh,
                                              int lane)
{
    const float4* h4 = reinterpret_cast<const float4*>(sh);
    float a0 = 0.f;
#pragma unroll
    for (int it = 0; it < 4; ++it) {
        F8 x = ld256_evl(w + it * 256 + lane * 8);
        a0 += f8_dot_sh(x, h4, it * 64 + lane * 2);
    }
    return warp_reduce_add(a0);
}

// streaming single-row dot (W_out leftover row)
__device__ __forceinline__ float warp_dot_evf(const float* __restrict__ w,
                                              const float* __restrict__ sh,
                                              int lane)
{
    const float4* h4 = reinterpret_cast<const float4*>(sh);
    float a0 = 0.f;
#pragma unroll
    for (int it = 0; it < 4; ++it) {
        F8 x = ld256_evf(w + it * 256 + lane * 8);
        a0 += f8_dot_sh(x, h4, it * 64 + lane * 2);
    }
    return warp_reduce_add(a0);
}

// two rows against two different vectors, evict_last (recurrent dots)
__device__ __forceinline__ void warp_dot_pair2_evl(const float* __restrict__ w1,
                                                   const float* __restrict__ s1,
                                                   const float* __restrict__ w2,
                                                   const float* __restrict__ s2,
                                                   int lane, float& o1, float& o2)
{
    const float4* h4 = reinterpret_cast<const float4*>(s1);
    const float4* g4 = reinterpret_cast<const float4*>(s2);
    float p = 0.f, q = 0.f;
#pragma unroll
    for (int it = 0; it < 4; ++it) {
        F8 a = ld256_evl(w1 + it * 256 + lane * 8);
        F8 b = ld256_evl(w2 + it * 256 + lane * 8);
        p += f8_dot_sh(a, h4, it * 64 + lane * 2);
        q += f8_dot_sh(b, g4, it * 64 + lane * 2);
    }
#pragma unroll
    for (int o = 16; o; o >>= 1) {
        p += __shfl_xor_sync(0xffffffffu, p, o);
        q += __shfl_xor_sync(0xffffffffu, q, o);
    }
    o1 = p; o2 = q;
}

// two independent W_out rows vs same vector; policy chosen per call (warp-uniform)
__device__ __forceinline__ void warp_dot_pair_pol(const float* __restrict__ w1,
                                                  const float* __restrict__ w2,
                                                  const float* __restrict__ sh,
                                                  int lane, bool cached,
                                                  float& o1, float& o2)
{
    const float4* h4 = reinterpret_cast<const float4*>(sh);
    float p = 0.f, q = 0.f;
    if (cached) {
#pragma unroll
        for (int it = 0; it < 4; ++it) {
            F8 a = ld256_evl(w1 + it * 256 + lane * 8);
            F8 b = ld256_evl(w2 + it * 256 + lane * 8);
            p += f8_dot_sh(a, h4, it * 64 + lane * 2);
            q += f8_dot_sh(b, h4, it * 64 + lane * 2);
        }
    } else {
#pragma unroll
        for (int it = 0; it < 4; ++it) {
            F8 a = ld256_evf(w1 + it * 256 + lane * 8);
            F8 b = ld256_evf(w2 + it * 256 + lane * 8);
            p += f8_dot_sh(a, h4, it * 64 + lane * 2);
            q += f8_dot_sh(b, h4, it * 64 + lane * 2);
        }
    }
#pragma unroll
    for (int o = 16; o; o >>= 1) {
        p += __shfl_xor_sync(0xffffffffu, p, o);
        q += __shfl_xor_sync(0xffffffffu, q, o);
    }
    o1 = p; o2 = q;
}

#define GRID_BARRIER() do {                                                  \
    __syncthreads();                                                         \
    if (tid == 0) {                                                          \
        __threadfence();                                                     \
        atomicAdd(&g_bar, 1ULL);                                             \
        bar_target += (unsigned long long)gridDim.x;                         \
        while (*((volatile unsigned long long*)&g_bar) < bar_target) { }     \
    }                                                                        \
    __syncthreads();                                                         \
} while (0)

__global__ void __launch_bounds__(NTHR, 1)
decoder_kernel(const int* __restrict__ y,
               const float* __restrict__ cv,
               const int* __restrict__ stride_p,
               const float* __restrict__ W_up,  const float* __restrict__ b_up,
               const float* __restrict__ W_ih0, const float* __restrict__ W_hh0,
               const float* __restrict__ b_ih0, const float* __restrict__ b_hh0,
               const float* __restrict__ W_ih1, const float* __restrict__ W_hh1,
               const float* __restrict__ b_ih1, const float* __restrict__ b_hh1,
               const float* __restrict__ W_out, const float* __restrict__ b_out,
               float* __restrict__ out)
{
    __shared__ __align__(16) float sh_h0[Hd];
    __shared__ __align__(16) float sh_h1[Hd];
    __shared__ __align__(16) float sh_c0[Hd];
    __shared__ __align__(16) float sh_c1[Hd];
    __shared__ float sh_pred[NWARP][8];   // per-warp deferred relu preds
    __shared__ float sh_red[NWARP];
    __shared__ unsigned long long sh_key[NWARP];
    __shared__ float sh_lse;

    const int tid  = threadIdx.x;
    const int bid  = blockIdx.x;
    const int wid  = tid >> 5;
    const int lane = tid & 31;
    const int gw   = bid * NWARP + wid;
    unsigned long long bar_target = 0ULL;

    const int nsteps = *stride_p;
    const int jrow = wid * NBLK + bid;     // gate row owned by this warp
    const bool dotsFirst = (gw & 1);       // stagger recurrent dots

    // ---------------- init: ctx = cv0*cv1 ; h_init = W_up @ ctx + b_up -----
    sh_h0[tid] = cv[tid] * cv[Hd + tid];
    __syncthreads();
    if (jrow < Hd) {
        float d = warp_dot(W_up + (size_t)jrow * Hd, sh_h0, lane);
        if (lane == 0) g_hinit[jrow] = d + b_up[jrow];
    }
    GRID_BARRIER();
    {
        float hv = __ldcv(&g_hinit[tid]);
        sh_h0[tid] = hv; sh_c0[tid] = hv; sh_h1[tid] = hv; sh_c1[tid] = hv;
    }
    __syncthreads();

    // initial recurrent dots for step 0 (hh0 -> g_gate0, hh1 partial -> reg)
    float q1 = 0.f;
    if (jrow < G4) {
        float p, q;
        warp_dot_pair2_evl(W_hh0 + (size_t)jrow * Hd, sh_h0,
                           W_hh1 + (size_t)jrow * Hd, sh_h1, lane, p, q);
        q1 = q;
        if (lane == 0)
            g_gate0[jrow] = p + b_ih0[jrow] + b_hh0[jrow];
    }
    GRID_BARRIER();

    for (int t = 0; t < nsteps; ++t) {
        // ---- A2: token, lse reduce (warp0), layer-0 cell (block-redundant) ----
        float tok;
        if (t == 0) {
            tok = (float)__ldg(&y[0]);
        } else {
            unsigned long long key = __ldcv(&g_argmax[t - 1]);
            tok = (float)(0xFFFFFFFFu - (unsigned)(key & 0xFFFFFFFFull));
        }
        if (t > 0 && wid == 0) {
            float s = 0.f;
            for (int k = lane; k < NBLK; k += 32)
                s += __ldcv(&g_partial[t - 1][k]);
            s = warp_reduce_add(s);
            if (lane == 0) sh_lse = logf(s);
        }
        {
            float pi = __ldcv(&g_gate0[tid])          + tok * __ldg(&W_ih0[tid]);
            float pf = __ldcv(&g_gate0[Hd + tid])     + tok * __ldg(&W_ih0[Hd + tid]);
            float pg = __ldcv(&g_gate0[2 * Hd + tid]) + tok * __ldg(&W_ih0[2 * Hd + tid]);
            float po = __ldcv(&g_gate0[3 * Hd + tid]) + tok * __ldg(&W_ih0[3 * Hd + tid]);
            float ig = sigmoidf_(pi);
            float fg = sigmoidf_(pf);
            float gg = tanhf(pg);
            float og = sigmoidf_(po);
            float c  = fg * sh_c0[tid] + ig * gg;
            sh_c0[tid] = c;
            sh_h0[tid] = og * tanhf(c);
        }
        __syncthreads();

        // ---- deferred coalesced write of step t-1 log-softmax ----
        if (t > 0 && wid < 7) {
            int r = bid * NWARP + lane + wid * TOTW;
            if (r < Vocab) {
                float v = sh_pred[lane][wid] - sh_lse;
                __stcs(&out[(size_t)(t - 1) * Vocab + r], v);
            }
        }

        // ---- phase B: only W_ih1·h0 on the critical path (L2-resident) ----
        if (jrow < G4) {
            float d = warp_dot_evl(W_ih1 + (size_t)jrow * Hd, sh_h0, lane);
            if (lane == 0)
                g_gate1[jrow] = q1 + d + b_ih1[jrow] + b_hh1[jrow];
        }
        GRID_BARRIER();

        // ---- B2: layer-1 cell (block-redundant) ----
        {
            float pi = __ldcv(&g_gate1[tid]);
            float pf = __ldcv(&g_gate1[Hd + tid]);
            float pg = __ldcv(&g_gate1[2 * Hd + tid]);
            float po = __ldcv(&g_gate1[3 * Hd + tid]);
            float ig = sigmoidf_(pi);
            float fg = sigmoidf_(pf);
            float gg = tanhf(pg);
            float og = sigmoidf_(po);
            float c  = fg * sh_c1[tid] + ig * gg;
            sh_c1[tid] = c;
            sh_h1[tid] = og * tanhf(c);
        }
        __syncthreads();

        // ---- phase C: vocab head + recurrent dots (staggered for mixing) ----
        if (dotsFirst && jrow < G4) {
            float p, q;
            warp_dot_pair2_evl(W_hh0 + (size_t)jrow * Hd, sh_h0,
                               W_hh1 + (size_t)jrow * Hd, sh_h1, lane, p, q);
            q1 = q;
            if (lane == 0)
                g_gate0[jrow] = p + b_ih0[jrow] + b_hh0[jrow];
        }

        float sumExp = 0.f;
        unsigned long long bestKey = 0ULL;
        int r = gw;
        int k = 0;
        int pr = 0;
        while (r + TOTW < Vocab) {
            // per-warp-parity choice of which pair stays L2-resident
            bool cached = dotsFirst ? (pr == 2) : (pr == 0);
            float d0, d1;
            warp_dot_pair_pol(W_out + (size_t)r * Hd,
                              W_out + (size_t)(r + TOTW) * Hd, sh_h1, lane,
                              cached, d0, d1);
            if (lane == 0) {
                float p0 = fmaxf(d0 + b_out[r], 0.f);
                float p1 = fmaxf(d1 + b_out[r + TOTW], 0.f);
                sh_pred[wid][k]     = p0;
                sh_pred[wid][k + 1] = p1;
                sumExp += expf(p0) + expf(p1);
                unsigned long long k0 =
                    ((unsigned long long)__float_as_uint(p0) << 32)
                    | (unsigned long long)(0xFFFFFFFFu - (unsigned)r);
                unsigned long long k1 =
                    ((unsigned long long)__float_as_uint(p1) << 32)
                    | (unsigned long long)(0xFFFFFFFFu - (unsigned)(r + TOTW));
                if (k0 > bestKey) bestKey = k0;
                if (k1 > bestKey) bestKey = k1;
            }
            r += 2 * TOTW;
            k += 2;
            pr++;
        }
        if (r < Vocab) {
            float d = warp_dot_evf(W_out + (size_t)r * Hd, sh_h1, lane);
            if (lane == 0) {
                float p = fmaxf(d + b_out[r], 0.f);
                sh_pred[wid][k] = p;
                sumExp += expf(p);
                unsigned long long kk =
                    ((unsigned long long)__float_as_uint(p) << 32)
                    | (unsigned long long)(0xFFFFFFFFu - (unsigned)r);
                if (kk > bestKey) bestKey = kk;
            }
        }

        if (!dotsFirst && jrow < G4) {
            float p, q;
            warp_dot_pair2_evl(W_hh0 + (size_t)jrow * Hd, sh_h0,
                               W_hh1 + (size_t)jrow * Hd, sh_h1, lane, p, q);
            q1 = q;
            if (lane == 0)
                g_gate0[jrow] = p + b_ih0[jrow] + b_hh0[jrow];
        }

        if (lane == 0) { sh_red[wid] = sumExp; sh_key[wid] = bestKey; }
        __syncthreads();
        if (wid == 0) {
            float s = sh_red[lane];
            unsigned long long kk = sh_key[lane];
#pragma unroll
            for (int o = 16; o; o >>= 1) {
                s += __shfl_xor_sync(0xffffffffu, s, o);
                unsigned long long k2 = __shfl_xor_sync(0xffffffffu, kk, o);
                if (k2 > kk) kk = k2;
            }
            if (lane == 0) {
                g_partial[t][bid] = s;
                atomicMax(&g_argmax[t], kk);
            }
        }
        GRID_BARRIER();
    }

    // ---- final: lse + deferred write for the last step ----
    if (wid == 0) {
        float s = 0.f;
        for (int kk = lane; kk < NBLK; kk += 32)
            s += __ldcv(&g_partial[nsteps - 1][kk]);
        s = warp_reduce_add(s);
        if (lane == 0) sh_lse = logf(s);
    }
    __syncthreads();
    if (wid < 7) {
        int r = bid * NWARP + lane + wid * TOTW;
        if (r < Vocab) {
            float v = sh_pred[lane][wid] - sh_lse;
            __stcs(&out[(size_t)(nsteps - 1) * Vocab + r], v);
        }
    }
}

extern "C" void kernel_launch(void* const* d_in, const int* in_sizes, int n_in,
                              void* d_out, int out_size)
{
    (void)in_sizes; (void)n_in; (void)out_size;
    dec_init<<<1, 256>>>();
    decoder_kernel<<<NBLK, NTHR>>>(
        (const int*)  d_in[0],   // y
        (const float*)d_in[1],   // context_vector
        (const int*)  d_in[2],   // stride
        (const float*)d_in[3],  (const float*)d_in[4],    // W_up, b_up
        (const float*)d_in[5],  (const float*)d_in[6],    // W_ih0, W_hh0
        (const float*)d_in[7],  (const float*)d_in[8],    // b_ih0, b_hh0
        (const float*)d_in[9],  (const float*)d_in[10],   // W_ih1, W_hh1
        (const float*)d_in[11], (const float*)d_in[12],   // b_ih1, b_hh1
        (const float*)d_in[13], (const float*)d_in[14],   // W_out, b_out
        (float*)d_out);
}